// round 14
// baseline (speedup 1.0000x reference)
#include <cuda_runtime.h>
#include <cuda_fp16.h>
#include <math.h>
#include <stdint.h>

// Problem constants
#define BB   4
#define NN   4096
#define CC   1024
#define HH   16
#define DDIM 64
#define BSZ  64
#define NBLK 64
#define MTOT (BB*NN)   // 16384

// ---------------- scratch (device globals, allocation-free) ------------------
__device__ __half g_xhi[(size_t)MTOT*CC];       // fp16(x)
__device__ __half g_whi[(size_t)4*CC*CC];       // Wq,Wk,Wv,Wo fp16
__device__ __half g_qh[(size_t)BB*HH*NN*DDIM];  // q/k/v split-fp16 [b][h][n][d]
__device__ __half g_ql[(size_t)BB*HH*NN*DDIM];
__device__ __half g_kh[(size_t)BB*HH*NN*DDIM];
__device__ __half g_kl[(size_t)BB*HH*NN*DDIM];
__device__ __half g_vh[(size_t)BB*HH*NN*DDIM];
__device__ __half g_vl[(size_t)BB*HH*NN*DDIM];
__device__ __half g_ohi[(size_t)MTOT*CC];       // attention out [m][c] (hi only)

// ---------------- PTX helpers (base sm_103 target only) ----------------------
__device__ __forceinline__ uint32_t smem_u32(const void* p) {
    uint32_t a;
    asm("{ .reg .u64 t; cvta.to.shared.u64 t, %1; cvt.u32.u64 %0, t; }"
        : "=r"(a) : "l"(p));
    return a;
}
__device__ __forceinline__ void ldsm4(unsigned* r, uint32_t addr) {
    asm volatile("ldmatrix.sync.aligned.m8n8.x4.shared.b16 {%0,%1,%2,%3}, [%4];"
                 : "=r"(r[0]), "=r"(r[1]), "=r"(r[2]), "=r"(r[3]) : "r"(addr));
}
__device__ __forceinline__ void ldsm4t(unsigned* r, uint32_t addr) {
    asm volatile("ldmatrix.sync.aligned.m8n8.x4.trans.shared.b16 {%0,%1,%2,%3}, [%4];"
                 : "=r"(r[0]), "=r"(r[1]), "=r"(r[2]), "=r"(r[3]) : "r"(addr));
}
__device__ __forceinline__ void mma16816_f32(float* d, const unsigned* a, const unsigned* b) {
    asm volatile(
        "mma.sync.aligned.m16n8k16.row.col.f32.f16.f16.f32 "
        "{%0,%1,%2,%3}, {%4,%5,%6,%7}, {%8,%9}, {%0,%1,%2,%3};"
        : "+f"(d[0]), "+f"(d[1]), "+f"(d[2]), "+f"(d[3])
        : "r"(a[0]), "r"(a[1]), "r"(a[2]), "r"(a[3]), "r"(b[0]), "r"(b[1]));
}
__device__ __forceinline__ void cpasync16(uint32_t saddr, const void* g) {
    asm volatile("cp.async.cg.shared.global [%0], [%1], 16;" :: "r"(saddr), "l"(g));
}
#define CP_COMMIT()  asm volatile("cp.async.commit_group;" ::: "memory")
#define CP_WAIT1()   asm volatile("cp.async.wait_group 1;" ::: "memory")
#define CP_WAIT0()   asm volatile("cp.async.wait_group 0;" ::: "memory")

// ---------------- fp32 -> fp16 conversion ------------------------------------
__global__ void convert_x(const float* __restrict__ src, int n4)
{
    int i = blockIdx.x * blockDim.x + threadIdx.x;
    if (i >= n4) return;
    float4 v = ((const float4*)src)[i];
    ((__half2*)g_xhi)[i * 2]     = __floats2half2_rn(v.x, v.y);
    ((__half2*)g_xhi)[i * 2 + 1] = __floats2half2_rn(v.z, v.w);
}
__global__ void convert_w(const float* __restrict__ Wq, const float* __restrict__ Wk,
                          const float* __restrict__ Wv, const float* __restrict__ Wo,
                          int per4)
{
    int i = blockIdx.x * blockDim.x + threadIdx.x;
    if (i >= 4 * per4) return;
    int wsel = i / per4;
    int j    = i - wsel * per4;
    const float* src = (wsel == 0) ? Wq : (wsel == 1) ? Wk : (wsel == 2) ? Wv : Wo;
    float4 v = ((const float4*)src)[j];
    __half* hi = g_whi + (size_t)wsel * CC * CC;
    ((__half2*)hi)[j * 2]     = __floats2half2_rn(v.x, v.y);
    ((__half2*)hi)[j * 2 + 1] = __floats2half2_rn(v.z, v.w);
}

// ---------------- HMMA single-product GEMM, BK=64, 3-stage -------------------
// OUT[m][c] = sum_k Xhi[m][k]*Whi[c][k] + bias[c]; CTA tile 128x128.
// 16 chunks of BK=64; 3-stage cp.async pipeline, ONE sync per chunk:
//   CP_WAIT1 (chunk ch resident) -> sync -> issue(ch+2) -> compute(ch).
// Stage (ch+2)%3 was last read in chunk ch-1; all warps passed that compute
// once through this iteration's barrier, so issue-after-sync is race-free.
// smem rows: 128B data padded to 144B (gcd(9,8)=1 -> conflict-free ldmatrix).
#define TILE_B 18432            // 128 * 144
#define STAGE_B (2 * TILE_B)    // 36864
#define GEMM_SMEM (3 * STAGE_B) // 110592
#define NCHUNK 16

template<int MODE>
__global__ __launch_bounds__(256, 2)
void gemm_mma(const float* __restrict__ b0,
              const float* __restrict__ b1,
              const float* __restrict__ b2,
              float* __restrict__ out)
{
    extern __shared__ char smc[];
    const uint32_t sb = smem_u32(smc);
    const int t    = threadIdx.x;
    const int w    = t >> 5;
    const int lane = t & 31;
    const int wm   = w & 3;
    const int wn   = w >> 2;
    const int m0   = blockIdx.x * 128;
    const int n0   = blockIdx.y * 128;
    const int widx = (MODE == 0) ? (int)blockIdx.z : 3;

    const __half* Ahi = (MODE == 0) ? g_xhi : g_ohi;
    const __half* Bhi = g_whi + (size_t)widx * CC * CC;
    const float* bias = b0;
    if (MODE == 0) { if (blockIdx.z == 1) bias = b1; else if (blockIdx.z == 2) bias = b2; }

    float acc[2][8][4];
#pragma unroll
    for (int a = 0; a < 2; a++)
#pragma unroll
        for (int n = 0; n < 8; n++)
#pragma unroll
            for (int k = 0; k < 4; k++) acc[a][n][k] = 0.f;

    const uint32_t aoff = (uint32_t)((lane & 15) * 144 + (lane >> 4) * 16);
    const uint32_t boff = (uint32_t)(((lane & 7) + (lane >> 4) * 8) * 144 + ((lane >> 3) & 1) * 16);

    // copy roles: 2 tiles * 128 rows * 8 chunks = 2048 / 256 thr = 8 each
    auto issue = [&](int ch) {
        const int k0 = ch * 64;
        const uint32_t stage = sb + (uint32_t)((ch % 3) * STAGE_B);
#pragma unroll
        for (int i = 0; i < 8; i++) {
            int id   = i * 256 + t;
            int tile = id >> 10;
            int idx  = id & 1023;
            int r    = idx >> 3;
            int c    = idx & 7;
            const __half* gp = tile ? Bhi : Ahi;
            int row = (tile ? n0 : m0) + r;
            cpasync16(stage + (uint32_t)(tile * TILE_B + r * 144 + c * 16),
                      gp + (size_t)row * CC + k0 + c * 8);
        }
        CP_COMMIT();
    };

    issue(0);
    issue(1);
    for (int ch = 0; ch < NCHUNK; ch++) {
        if (ch + 1 < NCHUNK) CP_WAIT1();   // chunk ch resident (<=1 younger pending)
        else                 CP_WAIT0();
        __syncthreads();
        if (ch + 2 < NCHUNK) issue(ch + 2);   // overlaps compute below

        const uint32_t stage = sb + (uint32_t)((ch % 3) * STAGE_B);
#pragma unroll
        for (int s = 0; s < 4; s++) {          // four k16 steps within BK=64
            unsigned ahi[2][4];
#pragma unroll
            for (int mt = 0; mt < 2; mt++)
                ldsm4(ahi[mt], stage + (uint32_t)((wm * 32 + mt * 16) * 144) + aoff + s * 32);
#pragma unroll
            for (int np = 0; np < 4; np++) {
                unsigned bhi[4];
                ldsm4(bhi, stage + TILE_B
                           + (uint32_t)((wn * 64 + np * 16) * 144) + boff + s * 32);
#pragma unroll
                for (int mt = 0; mt < 2; mt++) {
#pragma unroll
                    for (int nh = 0; nh < 2; nh++)
                        mma16816_f32(acc[mt][np * 2 + nh], ahi[mt], &bhi[2 * nh]);
                }
            }
        }
    }

    // epilogue
    __half* dsthi = g_qh;
    __half* dstlo = g_ql;
    if (MODE == 0) {
        if (blockIdx.z == 1)      { dsthi = g_kh; dstlo = g_kl; }
        else if (blockIdx.z == 2) { dsthi = g_vh; dstlo = g_vl; }
    }

#pragma unroll
    for (int mt = 0; mt < 2; mt++) {
#pragma unroll
        for (int nt = 0; nt < 8; nt++) {
            float* d = acc[mt][nt];
            const int col = n0 + wn * 64 + nt * 8 + 2 * (lane & 3);
            const float bv0 = bias[col], bv1 = bias[col + 1];
            const int r0 = m0 + wm * 32 + mt * 16 + (lane >> 2);
#pragma unroll
            for (int half = 0; half < 2; half++) {
                const int r = r0 + half * 8;
                float2 v = make_float2(d[2 * half] + bv0, d[2 * half + 1] + bv1);
                if (MODE == 0) {
                    const int bb  = r >> 12;
                    const int tok = r & (NN - 1);
                    const int h   = col >> 6;
                    const int dd  = col & 63;
                    __half2 hv = __floats2half2_rn(v.x, v.y);
                    float2 hf = __half22float2(hv);
                    __half2 lv = __floats2half2_rn(v.x - hf.x, v.y - hf.y);
                    size_t o = (((size_t)bb * HH + h) * NN + tok) * DDIM + dd;
                    *(__half2*)&dsthi[o] = hv;
                    *(__half2*)&dstlo[o] = lv;
                } else {
                    *(float2*)&out[(size_t)r * CC + col] = v;
                }
            }
        }
    }
}

// ---------------- Attention on HMMA: one CTA (128 thr) per (b, h, blk) -------
// Window = blocks [blk-1, blk] (right block fully causal-masked). 3-product
// split-fp16 MMA (error ~2^-22): qk = qh*kh + qh*kl + ql*kh; pv similarly.
#define AQH 0
#define AQL 9216
#define AKH 18432
#define AKL 36864
#define AVH 55296
#define AVL 73728
#define ATT_SMEM 92160

__global__ __launch_bounds__(128, 2)
void attn_mma()
{
    extern __shared__ char smc[];
    const uint32_t sb = smem_u32(smc);
    const int blk = blockIdx.x;
    const int hd  = blockIdx.y;
    const int b   = blockIdx.z;
    const int t   = threadIdx.x;
    const int w   = t >> 5;
    const int lane = t & 31;

    const size_t base = ((size_t)(b * HH + hd)) * NN * DDIM;

#pragma unroll
    for (int i = 0; i < 4; i++) {
        int id = i * 128 + t;
        int r = id >> 3, c = id & 7;
        size_t o = base + (size_t)(blk * BSZ + r) * DDIM;
        *(uint4*)(smc + AQH + r * 144 + c * 16) = *((const uint4*)(g_qh + o) + c);
        *(uint4*)(smc + AQL + r * 144 + c * 16) = *((const uint4*)(g_ql + o) + c);
    }
#pragma unroll
    for (int i = 0; i < 8; i++) {
        int id = i * 128 + t;
        int r = id >> 3, c = id & 7;
        int tokrel = (blk - 1) * BSZ + r;
        uint4 z = make_uint4(0u, 0u, 0u, 0u);
        uint4 kh = z, kl = z, vh = z, vl = z;
        if (tokrel >= 0) {
            size_t o = base + (size_t)tokrel * DDIM;
            kh = *((const uint4*)(g_kh + o) + c);
            kl = *((const uint4*)(g_kl + o) + c);
            vh = *((const uint4*)(g_vh + o) + c);
            vl = *((const uint4*)(g_vl + o) + c);
        }
        *(uint4*)(smc + AKH + r * 144 + c * 16) = kh;
        *(uint4*)(smc + AKL + r * 144 + c * 16) = kl;
        *(uint4*)(smc + AVH + r * 144 + c * 16) = vh;
        *(uint4*)(smc + AVL + r * 144 + c * 16) = vl;
    }
    __syncthreads();

    const int mw = w * 16;
    float sc[16][4];
#pragma unroll
    for (int j = 0; j < 16; j++)
#pragma unroll
        for (int k = 0; k < 4; k++) sc[j][k] = 0.f;

    const uint32_t aoffQ = (uint32_t)((mw + (lane & 15)) * 144 + (lane >> 4) * 16);
    const uint32_t boffK = (uint32_t)(((lane & 7) + (lane >> 4) * 8) * 144 + ((lane >> 3) & 1) * 16);

#pragma unroll
    for (int s = 0; s < 4; s++) {
        unsigned aq[4], al[4];
        ldsm4(aq, sb + AQH + aoffQ + s * 32);
        ldsm4(al, sb + AQL + aoffQ + s * 32);
#pragma unroll
        for (int g = 0; g < 8; g++) {
            unsigned bh[4], bl[4];
            uint32_t ka = sb + AKH + boffK + (uint32_t)(g * 16 * 144) + s * 32;
            ldsm4(bh, ka);
            ldsm4(bl, ka + (AKL - AKH));
#pragma unroll
            for (int nh = 0; nh < 2; nh++) {
                float* d = sc[g * 2 + nh];
                mma16816_f32(d, aq, &bh[2 * nh]);
                mma16816_f32(d, aq, &bl[2 * nh]);
                mma16816_f32(d, al, &bh[2 * nh]);
            }
        }
    }

    const int ilow = mw + (lane >> 2);
    const int c00  = 2 * (lane & 3);
    float mx0 = -1e30f, mx1 = -1e30f;
#pragma unroll
    for (int j = 0; j < 16; j++) {
        int c0 = j * 8 + c00;
        bool kv0 = (c0     >= 64) || (blk > 0);
        bool kv1 = (c0 + 1 >= 64) || (blk > 0);
        bool v0a = (c0     <= 64 + ilow) && kv0;
        bool v1a = (c0 + 1 <= 64 + ilow) && kv1;
        bool v0b = (c0     <= 72 + ilow) && kv0;
        bool v1b = (c0 + 1 <= 72 + ilow) && kv1;
        sc[j][0] = v0a ? sc[j][0] * 0.125f : -1e30f;
        sc[j][1] = v1a ? sc[j][1] * 0.125f : -1e30f;
        sc[j][2] = v0b ? sc[j][2] * 0.125f : -1e30f;
        sc[j][3] = v1b ? sc[j][3] * 0.125f : -1e30f;
        mx0 = fmaxf(mx0, fmaxf(sc[j][0], sc[j][1]));
        mx1 = fmaxf(mx1, fmaxf(sc[j][2], sc[j][3]));
    }
    mx0 = fmaxf(mx0, __shfl_xor_sync(0xffffffffu, mx0, 1));
    mx0 = fmaxf(mx0, __shfl_xor_sync(0xffffffffu, mx0, 2));
    mx1 = fmaxf(mx1, __shfl_xor_sync(0xffffffffu, mx1, 1));
    mx1 = fmaxf(mx1, __shfl_xor_sync(0xffffffffu, mx1, 2));

    float sm0 = 0.f, sm1 = 0.f;
#pragma unroll
    for (int j = 0; j < 16; j++) {
        sc[j][0] = __expf(sc[j][0] - mx0);
        sc[j][1] = __expf(sc[j][1] - mx0);
        sc[j][2] = __expf(sc[j][2] - mx1);
        sc[j][3] = __expf(sc[j][3] - mx1);
        sm0 += sc[j][0] + sc[j][1];
        sm1 += sc[j][2] + sc[j][3];
    }
    sm0 += __shfl_xor_sync(0xffffffffu, sm0, 1);
    sm0 += __shfl_xor_sync(0xffffffffu, sm0, 2);
    sm1 += __shfl_xor_sync(0xffffffffu, sm1, 1);
    sm1 += __shfl_xor_sync(0xffffffffu, sm1, 2);
    const float inv0 = 1.f / sm0, inv1 = 1.f / sm1;

    unsigned pa[8][4], pl[8][4];
#pragma unroll
    for (int j = 0; j < 8; j++) {
#pragma unroll
        for (int half = 0; half < 2; half++) {
            float p0 = sc[2 * j + half][0] * inv0;
            float p1 = sc[2 * j + half][1] * inv0;
            float p2 = sc[2 * j + half][2] * inv1;
            float p3 = sc[2 * j + half][3] * inv1;
            __half2 h01 = __floats2half2_rn(p0, p1);
            __half2 h23 = __floats2half2_rn(p2, p3);
            float2 f01 = __half22float2(h01);
            float2 f23 = __half22float2(h23);
            __half2 l01 = __floats2half2_rn(p0 - f01.x, p1 - f01.y);
            __half2 l23 = __floats2half2_rn(p2 - f23.x, p3 - f23.y);
            pa[j][2 * half]     = *(unsigned*)&h01;
            pa[j][2 * half + 1] = *(unsigned*)&h23;
            pl[j][2 * half]     = *(unsigned*)&l01;
            pl[j][2 * half + 1] = *(unsigned*)&l23;
        }
    }

    float oac[8][4];
#pragma unroll
    for (int n = 0; n < 8; n++)
#pragma unroll
        for (int k = 0; k < 4; k++) oac[n][k] = 0.f;

#pragma unroll
    for (int j = 0; j < 8; j++) {
#pragma unroll
        for (int g = 0; g < 4; g++) {
            unsigned bh[4], bl[4];
            uint32_t va = sb + AVH
                        + (uint32_t)((j * 16 + (lane & 15)) * 144)
                        + (uint32_t)((g * 16 + (lane >> 4) * 8) * 2);
            ldsm4t(bh, va);
            ldsm4t(bl, va + (AVL - AVH));
#pragma unroll
            for (int nh = 0; nh < 2; nh++) {
                float* d = oac[g * 2 + nh];
                mma16816_f32(d, pa[j], &bh[2 * nh]);
                mma16816_f32(d, pa[j], &bl[2 * nh]);
                mma16816_f32(d, pl[j], &bh[2 * nh]);
            }
        }
    }

#pragma unroll
    for (int nt = 0; nt < 8; nt++) {
        float* d = oac[nt];
        const int dd = nt * 8 + c00;
#pragma unroll
        for (int half = 0; half < 2; half++) {
            const int tok = blk * BSZ + ilow + half * 8;
            __half2 hv = __floats2half2_rn(d[2 * half], d[2 * half + 1]);
            size_t o = ((size_t)(b * NN) + tok) * CC + hd * DDIM + dd;
            *(__half2*)&g_ohi[o] = hv;
        }
    }
}

// ---------------- launch ------------------------------------------------------
extern "C" void kernel_launch(void* const* d_in, const int* in_sizes, int n_in,
                              void* d_out, int out_size)
{
    const float* x  = (const float*)d_in[0];
    const float* Wq = (const float*)d_in[1];
    const float* bq = (const float*)d_in[2];
    const float* Wk = (const float*)d_in[3];
    const float* bk = (const float*)d_in[4];
    const float* Wv = (const float*)d_in[5];
    const float* bv = (const float*)d_in[6];
    const float* Wo = (const float*)d_in[7];
    const float* bo = (const float*)d_in[8];
    float* out = (float*)d_out;

    cudaFuncSetAttribute(attn_mma,
                         cudaFuncAttributeMaxDynamicSharedMemorySize, ATT_SMEM);
    cudaFuncSetAttribute(gemm_mma<0>,
                         cudaFuncAttributeMaxDynamicSharedMemorySize, GEMM_SMEM);
    cudaFuncSetAttribute(gemm_mma<1>,
                         cudaFuncAttributeMaxDynamicSharedMemorySize, GEMM_SMEM);

    // fp32 -> fp16 (2 launches)
    {
        int n4 = MTOT * CC / 4;
        convert_x<<<(n4 + 255) / 256, 256>>>(x, n4);
        int w4 = CC * CC / 4;
        convert_w<<<(4 * w4 + 255) / 256, 256>>>(Wq, Wk, Wv, Wo, w4);
    }

    // QKV projections (HMMA single-product, BK=64, 3-stage), split-fp16 q/k/v
    dim3 g1(MTOT / 128, CC / 128, 3);
    gemm_mma<0><<<g1, 256, GEMM_SMEM>>>(bq, bk, bv, nullptr);

    // block-sparse attention on HMMA (3-product, fp32-equivalent)
    attn_mma<<<dim3(NBLK, HH, BB), 128, ATT_SMEM>>>();

    // output projection (single-product, BK=64, 3-stage)
    dim3 g2(MTOT / 128, CC / 128, 1);
    gemm_mma<1><<<g2, 256, GEMM_SMEM>>>(bo, nullptr, nullptr, out);
}